// round 16
// baseline (speedup 1.0000x reference)
#include <cuda_runtime.h>
#include <cuda_fp16.h>
#include <cstdint>

// DigitCapsules dynamic routing, GB300 sm_103a
// B=256, C=10, I=1152, DI=8, DO=16, 3 routing iterations.
//
// R16 = R15 + iteration-0 fused into uhat:
//   uhat (R15 structure: 16-i x 32-b blocks, FFMA2, coalesced stores) also
//   reduce-scatters Sum_i u over its 16 i-lanes (fp32, offsets 8/4/2/1) and
//   writes per-tile partials to private slots g_sp[b][c][itile][d]
//   (no atomics, no zeroing, coalesced 64B).
//   route streams u_hat only TWICE (iters 1,2); iter 0 becomes a tiny
//   prologue: sum 72 partials, x0.1, squash, shfl-broadcast.

#define BSZ  256
#define CCL  10
#define ICAP 1152
#define DOV  16
#define DIV  8
#define NT   (ICAP / 32)   // route: 36 tiles of 32 capsules

#define ITILE 16           // i's per uhat block
#define NTIL  (ICAP / ITILE)  // 72 i-tiles
#define BCH   32           // b's per uhat block
#define KSTR  20           // Wst k-stride (floats)
#define ISTR  164          // Wst i-stride (floats)

typedef unsigned long long ull;

__device__ __align__(256) __half g_uhat[(size_t)BSZ * CCL * ICAP * DOV]; // 94.4 MB
__device__ __align__(256) float g_sp[(size_t)BSZ * CCL * NTIL * DOV];    // 11.8 MB

// ---------------- packed f32x2 helpers (exact fp32 SIMD-2) ------------------
static __device__ __forceinline__ ull pack2(float x, float y) {
    ull r; asm("mov.b64 %0, {%1, %2};" : "=l"(r) : "f"(x), "f"(y)); return r;
}
static __device__ __forceinline__ void unpack2(ull v, float& x, float& y) {
    asm("mov.b64 {%0, %1}, %2;" : "=f"(x), "=f"(y) : "l"(v));
}
static __device__ __forceinline__ ull fma2(ull a, ull b, ull c) {
    ull d; asm("fma.rn.f32x2 %0, %1, %2, %3;" : "=l"(d) : "l"(a), "l"(b), "l"(c));
    return d;
}
static __device__ __forceinline__ unsigned int pack_h2(float a, float b) {
    __half2 h = __floats2half2_rn(a, b);
    return *reinterpret_cast<unsigned int*>(&h);
}

// reduce-scatter of 16 floats over 16 lanes (within half-warp).
// On return, lane with (lane&15)==d holds Sum over the 16 lanes of v[d].
static __device__ __forceinline__ float red_scatter16(const float* v, int lane) {
    float a[8], b[4], c2[2];
    #pragma unroll
    for (int j = 0; j < 8; j++) {
        float mine = (lane & 8) ? v[j + 8] : v[j];
        float send = (lane & 8) ? v[j]     : v[j + 8];
        a[j] = mine + __shfl_xor_sync(0xffffffffu, send, 8);
    }
    #pragma unroll
    for (int j = 0; j < 4; j++) {
        float mine = (lane & 4) ? a[j + 4] : a[j];
        float send = (lane & 4) ? a[j]     : a[j + 4];
        b[j] = mine + __shfl_xor_sync(0xffffffffu, send, 4);
    }
    #pragma unroll
    for (int j = 0; j < 2; j++) {
        float mine = (lane & 2) ? b[j + 2] : b[j];
        float send = (lane & 2) ? b[j]     : b[j + 2];
        c2[j] = mine + __shfl_xor_sync(0xffffffffu, send, 2);
    }
    float mine = (lane & 1) ? c2[1] : c2[0];
    float send = (lane & 1) ? c2[0] : c2[1];
    return mine + __shfl_xor_sync(0xffffffffu, send, 1);
}

// ---------------------------------------------------------------------------
// K_uhat: u_hat[b,c,i,:] = W[c,i] @ x[b,i]  + per-tile partial s0 sums.
// grid = 576 (72 i-tiles x 8 b-chunks), 256 threads = (b-pair, i).
// ---------------------------------------------------------------------------
__global__ __launch_bounds__(256) void uhat_kernel(
    const float* __restrict__ x, const float* __restrict__ W)
{
    __shared__ float Wst[ITILE * ISTR];   // [i][k][d] padded: 10496 B

    const int itile = blockIdx.x >> 3;
    const int i0 = itile * ITILE;
    const int b0 = (blockIdx.x & 7) * BCH;
    const int t  = threadIdx.x;
    const int bg = t >> 4;
    const int i  = t & 15;
    const int gi = i0 + i;
    const int bA = b0 + 2 * bg;

    float xr[2][8];
    #pragma unroll
    for (int p = 0; p < 2; p++) {
        const float4* xp = reinterpret_cast<const float4*>(
            x + (size_t)(bA + p) * (ICAP * DIV) + (size_t)gi * DIV);
        float4 a = xp[0], bq = xp[1];
        xr[p][0] = a.x;  xr[p][1] = a.y;  xr[p][2] = a.z;  xr[p][3] = a.w;
        xr[p][4] = bq.x; xr[p][5] = bq.y; xr[p][6] = bq.z; xr[p][7] = bq.w;
    }

    #pragma unroll 1
    for (int c = 0; c < CCL; c++) {
        __syncthreads();
        for (int e = t; e < ITILE * DOV * DIV; e += 256) {
            int ie = e >> 7;
            int dk = e & 127;
            int d  = dk >> 3, k = dk & 7;
            Wst[ie * ISTR + k * KSTR + d] =
                W[(size_t)c * (ICAP * DOV * DIV) + (size_t)(i0 + ie) * 128 + dk];
        }
        __syncthreads();

        #pragma unroll
        for (int p = 0; p < 2; p++) {
            ull acc[8];
            #pragma unroll
            for (int j = 0; j < 8; j++) acc[j] = 0ULL;

            #pragma unroll
            for (int k = 0; k < DIV; k++) {
                const ull xx = pack2(xr[p][k], xr[p][k]);
                const ull* wk = reinterpret_cast<const ull*>(
                    Wst + i * ISTR + k * KSTR);
                #pragma unroll
                for (int j = 0; j < 8; j++) acc[j] = fma2(wk[j], xx, acc[j]);
            }

            float r[DOV];
            unsigned int h[8];
            #pragma unroll
            for (int j = 0; j < 8; j++) {
                unpack2(acc[j], r[2 * j], r[2 * j + 1]);
                h[j] = pack_h2(r[2 * j], r[2 * j + 1]);
            }
            __half* o = g_uhat
                + (((size_t)(bA + p) * CCL + c) * ICAP + gi) * DOV;
            *reinterpret_cast<uint4*>(o)     = make_uint4(h[0], h[1], h[2], h[3]);
            *reinterpret_cast<uint4*>(o + 8) = make_uint4(h[4], h[5], h[6], h[7]);

            // per-tile partial Sum_i u (fp32): lane i ends owning d=i
            float part = red_scatter16(r, i);
            g_sp[(((size_t)(bA + p) * CCL + c) * NTIL + itile) * DOV + i] = part;
        }
    }
}

// ---------------------------------------------------------------------------
// route_kernel: prologue computes v0 from g_sp partials, then iterations 1,2
// stream u_hat (R4 inner loop verbatim: prefetch, double-buffered e_s).
// grid = B, 320 threads: warp = class, lane = capsule slot.
// ---------------------------------------------------------------------------
static __device__ __forceinline__ void unpack16(const uint4& a, const uint4& b,
                                                float* __restrict__ u) {
    const __half2* ha = reinterpret_cast<const __half2*>(&a);
    const __half2* hb = reinterpret_cast<const __half2*>(&b);
    #pragma unroll
    for (int q = 0; q < 4; q++) {
        float2 f = __half22float2(ha[q]);
        u[q * 2] = f.x; u[q * 2 + 1] = f.y;
    }
    #pragma unroll
    for (int q = 0; q < 4; q++) {
        float2 f = __half22float2(hb[q]);
        u[8 + q * 2] = f.x; u[8 + q * 2 + 1] = f.y;
    }
}

__global__ __launch_bounds__(320, 2) void route_kernel(float* __restrict__ out)
{
    const int b  = blockIdx.x;
    const int c  = threadIdx.x >> 5;
    const int ii = threadIdx.x & 31;

    __shared__ float e_s[2][CCL][33];

    const __half* ub = g_uhat + ((size_t)b * CCL + c) * (size_t)ICAP * DOV;

    // ---------------- prologue: v0 = squash(0.1 * Sum of tile partials)
    float vr[DOV];
    {
        const int d    = ii & 15;
        const int half = ii >> 4;     // lanes 0-15: tiles 0-35; 16-31: 36-71
        const float* sp = g_sp + ((size_t)b * CCL + c) * (NTIL * DOV) + d;
        float acc = 0.0f;
        #pragma unroll 4
        for (int it = half * 36; it < half * 36 + 36; it++)
            acc += sp[(size_t)it * DOV];
        acc += __shfl_xor_sync(0xffffffffu, acc, 16);
        float s0 = 0.1f * acc;        // iteration-0 s (uniform weights)

        float sq = s0 * s0;
        #pragma unroll
        for (int off = 1; off < 16; off <<= 1)
            sq += __shfl_xor_sync(0xffffffffu, sq, off);
        float scale = __fdividef(sqrtf(sq), 1.0f + sq);

        #pragma unroll
        for (int j = 0; j < DOV; j++)
            vr[j] = scale * __shfl_sync(0xffffffffu, s0, j);
    }

    float sac[DOV];

    // ---------------- iterations 1 and 2
    #pragma unroll 1
    for (int t = 1; t < 3; t++) {
        #pragma unroll
        for (int j = 0; j < DOV; j++) sac[j] = 0.0f;

        const uint4* p0 = reinterpret_cast<const uint4*>(ub + (size_t)ii * DOV);
        uint4 ua = p0[0], ux = p0[1];

        for (int ti = 0; ti < NT; ti++) {
            const int tn = (ti + 1 < NT) ? (ti + 1) : (NT - 1);
            const uint4* pn = reinterpret_cast<const uint4*>(
                ub + (size_t)(tn * 32 + ii) * DOV);
            uint4 na = pn[0], nb = pn[1];

            float u[DOV];
            unpack16(ua, ux, u);

            float a = u[0] * vr[0];
            #pragma unroll
            for (int j = 1; j < DOV; j++) a = fmaf(u[j], vr[j], a);
            // |logit| bounded (~35): exp safe in fp32 without max-subtract
            float e = __expf(a);
            const int pb = ti & 1;
            e_s[pb][c][ii] = e;
            __syncthreads();
            float Z = e_s[pb][0][ii];
            #pragma unroll
            for (int cc = 1; cc < CCL; cc++) Z += e_s[pb][cc][ii];
            float w = __fdividef(e, Z);

            #pragma unroll
            for (int j = 0; j < DOV; j++) sac[j] = fmaf(w, u[j], sac[j]);

            ua = na; ux = nb;
        }

        #pragma unroll
        for (int off = 16; off > 0; off >>= 1)
            #pragma unroll
            for (int j = 0; j < DOV; j++)
                sac[j] += __shfl_xor_sync(0xffffffffu, sac[j], off);

        float sq = 0.0f;
        #pragma unroll
        for (int j = 0; j < DOV; j++) sq = fmaf(sac[j], sac[j], sq);
        float scale = __fdividef(sqrtf(sq), 1.0f + sq);

        if (t == 2) {
            if (ii == 0) {
                float4* op = reinterpret_cast<float4*>(
                    out + ((size_t)b * CCL + c) * DOV);
                op[0] = make_float4(sac[0]*scale,  sac[1]*scale,  sac[2]*scale,  sac[3]*scale);
                op[1] = make_float4(sac[4]*scale,  sac[5]*scale,  sac[6]*scale,  sac[7]*scale);
                op[2] = make_float4(sac[8]*scale,  sac[9]*scale,  sac[10]*scale, sac[11]*scale);
                op[3] = make_float4(sac[12]*scale, sac[13]*scale, sac[14]*scale, sac[15]*scale);
            }
        } else {
            #pragma unroll
            for (int j = 0; j < DOV; j++) vr[j] += sac[j] * scale;
        }
    }
}

// ---------------------------------------------------------------------------
extern "C" void kernel_launch(void* const* d_in, const int* in_sizes, int n_in,
                              void* d_out, int out_size)
{
    const float* x = (const float*)d_in[0];
    const float* W = (const float*)d_in[1];
    if (in_sizes[0] == CCL * ICAP * DOV * DIV) {  // defensively identify by size
        const float* t = x; x = W; W = t;
    }
    float* out = (float*)d_out;

    uhat_kernel<<<NTIL * (BSZ / BCH), 256>>>(x, W);
    route_kernel<<<BSZ, 320>>>(out);
}